// round 13
// baseline (speedup 1.0000x reference)
#include <cuda_runtime.h>

#define CCLS 19
#define NIMG 4
#define HW   589824            /* 768*768 */
#define TOT  2359296           /* NIMG*HW */
#define GPI  147456            /* float4-groups per image (HW/4) */
#define TGP  589824            /* total float4-groups (NIMG*GPI) */

#define NTHR 256
#define NWRP 8
#define NBLK 740               /* 148 SMs * 5 resident = exactly one wave */
#define ABPI 185               /* phase-A blocks per image (NBLK/NIMG) */

// ---- static device scratch (no allocs) ----
__device__ unsigned char g_idx[TOT];          // per-pixel: tc + 19*(edge>0.8)
__device__ unsigned int  g_cnt38[NIMG][38];   // [n][idx] counts (int atomics, exact)
__device__ double g_bp, g_bn;
__device__ unsigned long long g_pc;
__device__ float  g_w[NIMG][38];              // [c]: wseg/den ; [19+c]: + 0.1*watt/denatt
__device__ double g_loss;
__device__ unsigned int g_c1 = 0, g_c2 = 0;   // arrival counters (self-resetting)
__device__ unsigned int g_flag = 0;           // phase-A-complete flag (self-resetting)

__global__ __launch_bounds__(NTHR, 5) void fused_kernel(
    const float* __restrict__ segin, const float* __restrict__ edgein,
    const int* __restrict__ segmask, const int* __restrict__ edgemask,
    float* __restrict__ out, int out_size)
{
    // ---- shared (phase A hist + phase A epilogue + phase B) ----
    __shared__ unsigned int cnt[38][NTHR];    // conflict-free per-thread columns
    __shared__ float  sbp[NWRP], sbn[NWRP];
    __shared__ unsigned int spc[NWRP];
    __shared__ unsigned int lastv;
    __shared__ float sc[NIMG][38];
    __shared__ float dens[NIMG], dena[NIMG], tots[NIMG], tota[NIMG];
    __shared__ float sw[NIMG * 38];
    __shared__ double rs[NWRP];

    const int t = threadIdx.x;
    const int wid = t >> 5, lid = t & 31;

    // ================= PHASE A: histogram + BCE + idx pack =================
    const int bimg = blockIdx.x / ABPI;            // image 0..3
    const int bloc = blockIdx.x - bimg * ABPI;     // 0..184

    #pragma unroll
    for (int i = 0; i < 38; i++) cnt[i][t] = 0u;   // own column: no sync needed

    {
        const int4*   sm4 = (const int4*)(segmask + (size_t)bimg * HW);
        const float4* e4p = (const float4*)(edgein  + (size_t)bimg * HW);
        const int4*   em4 = (const int4*)(edgemask + (size_t)bimg * HW);
        uchar4*       id4 = (uchar4*)g_idx + (size_t)bimg * GPI;

        float bp = 0.f, bn = 0.f; unsigned int pc = 0;

        for (int gi = bloc * NTHR + t; gi < GPI; gi += ABPI * NTHR) {
            const int4   tc = sm4[gi];
            const float4 e  = e4p[gi];
            const int4   em = em4[gi];

            const int i0 = tc.x + (e.x > 0.8f ? CCLS : 0);
            const int i1 = tc.y + (e.y > 0.8f ? CCLS : 0);
            const int i2 = tc.z + (e.z > 0.8f ? CCLS : 0);
            const int i3 = tc.w + (e.w > 0.8f ? CCLS : 0);
            cnt[i0][t]++; cnt[i1][t]++; cnt[i2][t]++; cnt[i3][t]++;
            id4[gi] = make_uchar4((unsigned char)i0, (unsigned char)i1,
                                  (unsigned char)i2, (unsigned char)i3);

            #define BCE_PX(EJ, EMJ) do {                                      \
                const float bce = fmaxf((EJ), 0.f) - (EJ) * (float)(EMJ)      \
                                + __logf(1.f + __expf(-fabsf(EJ)));           \
                bp += (EMJ) ? bce : 0.f;                                      \
                bn += (EMJ) ? 0.f : bce;                                      \
                pc += (unsigned)(EMJ);                                        \
            } while (0)
            BCE_PX(e.x, em.x); BCE_PX(e.y, em.y); BCE_PX(e.z, em.z); BCE_PX(e.w, em.w);
            #undef BCE_PX
        }
        __syncthreads();

        // per-class reduce: warp w handles rows w, w+8, ...
        for (int c = wid; c < 38; c += NWRP) {
            unsigned int s = 0;
            #pragma unroll
            for (int k = 0; k < NTHR / 32; k++) s += cnt[c][lid + 32 * k];
            #pragma unroll
            for (int o = 16; o; o >>= 1) s += __shfl_down_sync(0xffffffffu, s, o);
            if (lid == 0 && s) atomicAdd(&g_cnt38[bimg][c], s);
        }

        // BCE reduce
        #pragma unroll
        for (int o = 16; o; o >>= 1) {
            bp += __shfl_down_sync(0xffffffffu, bp, o);
            bn += __shfl_down_sync(0xffffffffu, bn, o);
            pc += __shfl_down_sync(0xffffffffu, pc, o);
        }
        if (lid == 0) { sbp[wid] = bp; sbn[wid] = bn; spc[wid] = pc; }
        __syncthreads();
        if (t == 0) {
            float tp = 0.f, tn = 0.f; unsigned int tpc = 0;
            #pragma unroll
            for (int w = 0; w < NWRP; w++) { tp += sbp[w]; tn += sbn[w]; tpc += spc[w]; }
            atomicAdd(&g_bp, (double)tp);
            atomicAdd(&g_bn, (double)tn);
            atomicAdd(&g_pc, (unsigned long long)tpc);
        }
    }

    __threadfence();
    if (t == 0) lastv = atomicAdd(&g_c1, 1u);
    __syncthreads();

    if (lastv == NBLK - 1) {
        // ---- last block: weights + edge-loss epilogue ----
        __threadfence();
        if (t < NIMG * 38) {
            const int ni = t / 38, c = t - ni * 38;
            sc[ni][c] = (float)g_cnt38[ni][c];   // counts < 2^24: exact
            g_cnt38[ni][c] = 0u;                 // reset for next replay
        }
        __syncthreads();
        if (t < NIMG) {
            float tot = 0.f, ta = 0.f;
            #pragma unroll
            for (int c = 0; c < CCLS; c++) { tot += sc[t][c] + sc[t][CCLS + c]; ta += sc[t][CCLS + c]; }
            float ds = 0.f, da = 0.f;
            #pragma unroll
            for (int c = 0; c < CCLS; c++) {
                const float cs = sc[t][c] + sc[t][CCLS + c];
                const float ca = sc[t][CCLS + c];
                ds += (2.f - cs / tot) * cs;
                if (ta > 0.f) da += (2.f - ca / ta) * ca;
            }
            tots[t] = tot; tota[t] = ta; dens[t] = ds; dena[t] = da;
        }
        __syncthreads();
        if (t < NIMG * CCLS) {
            const int ni = t / CCLS, c = t - ni * CCLS;
            const float cs = sc[ni][c] + sc[ni][CCLS + c];
            const float ca = sc[ni][CCLS + c];
            const float ws = (2.f - cs / tots[ni]) / dens[ni];
            const float wa = (dena[ni] > 0.f) ? 0.1f * (2.f - ca / tota[ni]) / dena[ni] : 0.f;
            g_w[ni][c]        = ws;
            g_w[ni][CCLS + c] = ws + wa;
        }
        if (t == 0) {
            const double posn = (double)g_pc, negn = (double)TOT - posn;
            g_loss = 0.3 * (negn * g_bp + posn * g_bn) / ((double)TOT * (double)TOT);
            g_bp = 0.0; g_bn = 0.0; g_pc = 0ull;
        }
        __syncthreads();
        if (t == 0) { __threadfence(); atomicExch(&g_flag, 1u); }
    } else {
        // ---- other blocks: spin until weights published (all resident: safe) ----
        if (t == 0) {
            while (((volatile unsigned int*)&g_flag)[0] == 0u) __nanosleep(64);
            __threadfence();
        }
        __syncthreads();
    }

    // ================= PHASE B: heavy pass over segin =================
    if (t < NIMG * 38) sw[t] = ((const float*)g_w)[t];
    __syncthreads();

    const float4* s4 = (const float4*)segin;
    const uchar4* i4 = (const uchar4*)g_idx;

    float acc = 0.f;

    #pragma unroll 1
    for (int g = blockIdx.x * NTHR + t; g < TGP; g += NBLK * NTHR) {
        const int n = g / GPI;                       // 0..3, mul-shift
        const uchar4 id = i4[g];
        const float4* base = s4 + (size_t)n * (18 * GPI) + g;  // = n*19*GPI + gi

        const int t0 = id.x - (id.x >= CCLS ? CCLS : 0);
        const int t1 = id.y - (id.y >= CCLS ? CCLS : 0);
        const int t2 = id.z - (id.z >= CCLS ? CCLS : 0);
        const int t3 = id.w - (id.w >= CCLS ? CCLS : 0);

        float s0 = 0.f, s1 = 0.f, s2 = 0.f, s3 = 0.f;
        float x0 = 0.f, x1 = 0.f, x2 = 0.f, x3 = 0.f;
        #pragma unroll
        for (int c = 0; c < CCLS; c++) {
            const float4 v = __ldcs((const float4*)(base + (size_t)c * GPI));
            s0 += __expf(v.x); x0 = (c == t0) ? v.x : x0;
            s1 += __expf(v.y); x1 = (c == t1) ? v.y : x1;
            s2 += __expf(v.z); x2 = (c == t2) ? v.z : x2;
            s3 += __expf(v.w); x3 = (c == t3) ? v.w : x3;
        }
        const float* swn = &sw[n * 38];
        acc += (x0 - __logf(s0)) * swn[id.x]
             + (x1 - __logf(s1)) * swn[id.y]
             + (x2 - __logf(s2)) * swn[id.z]
             + (x3 - __logf(s3)) * swn[id.w];
    }

    #pragma unroll
    for (int o = 16; o; o >>= 1) acc += __shfl_down_sync(0xffffffffu, acc, o);
    if (lid == 0) rs[wid] = (double)acc;
    __syncthreads();

    if (t == 0) {
        double ts = 0.0;
        #pragma unroll
        for (int w = 0; w < NWRP; w++) ts += rs[w];
        atomicAdd(&g_loss, -ts);                    // NLL sign
        __threadfence();
        lastv = atomicAdd(&g_c2, 1u);
    }
    __syncthreads();
    if (lastv != NBLK - 1) return;

    // ---- final epilogue: write output, reset sync state ----
    __threadfence();
    for (int i = t; i < out_size; i += NTHR) out[i] = 0.f;
    __syncthreads();
    if (t == 0) {
        out[0] = (float)g_loss;
        g_c1 = 0u; g_c2 = 0u; g_flag = 0u;          // reset for next graph replay
    }
}

extern "C" void kernel_launch(void* const* d_in, const int* in_sizes, int n_in,
                              void* d_out, int out_size) {
    const float* segin    = (const float*)d_in[0];
    const float* edgein   = (const float*)d_in[1];
    const int*   segmask  = (const int*)d_in[2];
    const int*   edgemask = (const int*)d_in[3];
    float* out = (float*)d_out;

    fused_kernel<<<NBLK, NTHR>>>(segin, edgein, segmask, edgemask, out, out_size);
}

// round 14
// speedup vs baseline: 1.4399x; 1.4399x over previous
#include <cuda_runtime.h>

#define CCLS 19
#define NIMG 4
#define HW   589824            /* 768*768 */
#define TOT  2359296           /* NIMG*HW */
#define GPI  147456            /* float4-groups per image (HW/4) */
#define TGP  589824            /* total float4-groups (NIMG*GPI) */

#define HTHR 256               /* hist threads/block */
#define HB   296               /* hist blocks per image: 4*296=1184 = 148 SMs * 8 */
#define NHB  (NIMG*HB)         /* 1184 = exactly one wave at 8 blocks/SM */
#define HWRP (HTHR/32)         /* 8 */

#define MTHR 256               /* main threads/block */
#define NMB  740               /* main blocks = 148 SMs * 5 resident, 1 wave */
#define MWRP (MTHR/32)         /* 8 */

// ---- static device scratch (no allocs) ----
__device__ unsigned char g_idx[TOT];          // per-pixel: tc + 19*(edge>0.8)
__device__ unsigned int  g_cnt38[NIMG][38];   // [n][idx] counts (int atomics, exact)
__device__ double g_bp, g_bn;
__device__ unsigned long long g_pc;
__device__ float  g_w[NIMG][38];              // [c]: wseg/den ; [19+c]: + 0.1*watt/denatt
__device__ double g_loss;
__device__ unsigned int g_c1 = 0, g_c2 = 0;   // self-resetting arrival counters

// ============================================================
// Kernel 1: histogram + BCE + idx pack; last block: weights + edge loss.
// Per-warp bins + shared atomics (1.2KB smem -> 8 blocks/SM, full wave).
// ============================================================
__global__ __launch_bounds__(HTHR) void hist_kernel(
    const int* __restrict__ segmask, const float* __restrict__ edgein,
    const int* __restrict__ edgemask)
{
    __shared__ unsigned int cnt[HWRP][38];    // per-warp bins (spread-addr atomics)
    __shared__ float  sbp[HWRP], sbn[HWRP];
    __shared__ unsigned int spc[HWRP];

    const int n = blockIdx.y, b = blockIdx.x, t = threadIdx.x;
    const int wid = t >> 5, lid = t & 31;

    for (int i = t; i < HWRP * 38; i += HTHR) ((unsigned int*)cnt)[i] = 0u;
    __syncthreads();

    const int4*   sm4 = (const int4*)(segmask + (size_t)n * HW);
    const float4* e4p = (const float4*)(edgein  + (size_t)n * HW);
    const int4*   em4 = (const int4*)(edgemask + (size_t)n * HW);
    uchar4*       id4 = (uchar4*)g_idx + (size_t)n * GPI;

    float bp = 0.f, bn = 0.f; unsigned int pc = 0;

    for (int gi = b * HTHR + t; gi < GPI; gi += HB * HTHR) {
        const int4   tc = sm4[gi];
        const float4 e  = e4p[gi];
        const int4   em = em4[gi];

        const int i0 = tc.x + (e.x > 0.8f ? CCLS : 0);
        const int i1 = tc.y + (e.y > 0.8f ? CCLS : 0);
        const int i2 = tc.z + (e.z > 0.8f ? CCLS : 0);
        const int i3 = tc.w + (e.w > 0.8f ? CCLS : 0);
        atomicAdd(&cnt[wid][i0], 1u);
        atomicAdd(&cnt[wid][i1], 1u);
        atomicAdd(&cnt[wid][i2], 1u);
        atomicAdd(&cnt[wid][i3], 1u);
        id4[gi] = make_uchar4((unsigned char)i0, (unsigned char)i1,
                              (unsigned char)i2, (unsigned char)i3);

        #define BCE_PX(EJ, EMJ) do {                                          \
            const float bce = fmaxf((EJ), 0.f) - (EJ) * (float)(EMJ)          \
                            + __logf(1.f + __expf(-fabsf(EJ)));               \
            bp += (EMJ) ? bce : 0.f;                                          \
            bn += (EMJ) ? 0.f : bce;                                          \
            pc += (unsigned)(EMJ);                                            \
        } while (0)
        BCE_PX(e.x, em.x); BCE_PX(e.y, em.y); BCE_PX(e.z, em.z); BCE_PX(e.w, em.w);
        #undef BCE_PX
    }
    __syncthreads();

    // per-class reduce: 38 threads sum the 8 warp bins, one global atomic each
    if (t < 38) {
        unsigned int s = 0;
        #pragma unroll
        for (int w = 0; w < HWRP; w++) s += cnt[w][t];
        if (s) atomicAdd(&g_cnt38[n][t], s);
    }

    // BCE reduce: shuffle -> shared -> 3 global atomics per block
    #pragma unroll
    for (int o = 16; o; o >>= 1) {
        bp += __shfl_down_sync(0xffffffffu, bp, o);
        bn += __shfl_down_sync(0xffffffffu, bn, o);
        pc += __shfl_down_sync(0xffffffffu, pc, o);
    }
    if (lid == 0) { sbp[wid] = bp; sbn[wid] = bn; spc[wid] = pc; }
    __syncthreads();
    if (t == 0) {
        float tp = 0.f, tn = 0.f; unsigned int tpc = 0;
        #pragma unroll
        for (int w = 0; w < HWRP; w++) { tp += sbp[w]; tn += sbn[w]; tpc += spc[w]; }
        atomicAdd(&g_bp, (double)tp);
        atomicAdd(&g_bn, (double)tn);
        atomicAdd(&g_pc, (unsigned long long)tpc);
    }

    __threadfence();
    __shared__ unsigned int lastv;
    if (t == 0) lastv = atomicAdd(&g_c1, 1u);
    __syncthreads();
    if (lastv != NHB - 1) return;

    // ---------- epilogue: one block, tiny data ----------
    __threadfence();
    __shared__ float sc[NIMG][38];
    __shared__ float dens[NIMG], dena[NIMG], tots[NIMG], tota[NIMG];

    if (t < NIMG * 38) {
        const int ni = t / 38, c = t - ni * 38;
        sc[ni][c] = (float)g_cnt38[ni][c];   // counts < 2^24: exact
        g_cnt38[ni][c] = 0u;                 // reset for next replay
    }
    __syncthreads();
    if (t < NIMG) {
        float tot = 0.f, ta = 0.f;
        #pragma unroll
        for (int c = 0; c < CCLS; c++) { tot += sc[t][c] + sc[t][CCLS + c]; ta += sc[t][CCLS + c]; }
        float ds = 0.f, da = 0.f;
        #pragma unroll
        for (int c = 0; c < CCLS; c++) {
            const float cs = sc[t][c] + sc[t][CCLS + c];
            const float ca = sc[t][CCLS + c];
            ds += (2.f - cs / tot) * cs;
            if (ta > 0.f) da += (2.f - ca / ta) * ca;
        }
        tots[t] = tot; tota[t] = ta; dens[t] = ds; dena[t] = da;
    }
    __syncthreads();
    if (t < NIMG * CCLS) {
        const int ni = t / CCLS, c = t - ni * CCLS;
        const float cs = sc[ni][c] + sc[ni][CCLS + c];
        const float ca = sc[ni][CCLS + c];
        const float ws = (2.f - cs / tots[ni]) / dens[ni];
        const float wa = (dena[ni] > 0.f) ? 0.1f * (2.f - ca / tota[ni]) / dena[ni] : 0.f;
        g_w[ni][c]        = ws;
        g_w[ni][CCLS + c] = ws + wa;
    }
    if (t == 0) {
        const double posn = (double)g_pc, negn = (double)TOT - posn;
        g_loss = 0.3 * (negn * g_bp + posn * g_bn) / ((double)TOT * (double)TOT);
        g_bp = 0.0; g_bn = 0.0; g_pc = 0ull;
        g_c1 = 0u;
    }
}

// ============================================================
// Kernel 2: heavy pass over segin (+2.4MB idx). R12-proven config:
// single stream, 740 blocks, 5/SM (48 regs), 1 wave. 34.3-34.8us measured.
// ============================================================
__global__ __launch_bounds__(MTHR, 5) void main_kernel(
    const float* __restrict__ segin, float* __restrict__ out, int out_size)
{
    __shared__ float sw[NIMG][38];
    __shared__ double rs[MWRP];
    const int t = threadIdx.x;
    if (t < NIMG * 38) ((float*)sw)[t] = ((const float*)g_w)[t];
    __syncthreads();

    const float4* s4 = (const float4*)segin;
    const uchar4* i4 = (const uchar4*)g_idx;

    float acc = 0.f;

    #pragma unroll 1
    for (int g = blockIdx.x * MTHR + t; g < TGP; g += NMB * MTHR) {
        const int n = g / GPI;                       // 0..3, mul-shift
        const uchar4 id = i4[g];
        const float4* base = s4 + (size_t)n * (18 * GPI) + g;  // = n*19*GPI + gi

        const int t0 = id.x - (id.x >= CCLS ? CCLS : 0);
        const int t1 = id.y - (id.y >= CCLS ? CCLS : 0);
        const int t2 = id.z - (id.z >= CCLS ? CCLS : 0);
        const int t3 = id.w - (id.w >= CCLS ? CCLS : 0);

        float s0 = 0.f, s1 = 0.f, s2 = 0.f, s3 = 0.f;
        float x0 = 0.f, x1 = 0.f, x2 = 0.f, x3 = 0.f;
        #pragma unroll
        for (int c = 0; c < CCLS; c++) {
            const float4 v = __ldcs((const float4*)(base + (size_t)c * GPI));
            s0 += __expf(v.x); x0 = (c == t0) ? v.x : x0;
            s1 += __expf(v.y); x1 = (c == t1) ? v.y : x1;
            s2 += __expf(v.z); x2 = (c == t2) ? v.z : x2;
            s3 += __expf(v.w); x3 = (c == t3) ? v.w : x3;
        }
        const float* swn = &sw[n][0];
        acc += (x0 - __logf(s0)) * swn[id.x]
             + (x1 - __logf(s1)) * swn[id.y]
             + (x2 - __logf(s2)) * swn[id.z]
             + (x3 - __logf(s3)) * swn[id.w];
    }

    #pragma unroll
    for (int o = 16; o; o >>= 1) acc += __shfl_down_sync(0xffffffffu, acc, o);
    const int wid = t >> 5, lid = t & 31;
    if (lid == 0) rs[wid] = (double)acc;
    __syncthreads();

    __shared__ unsigned int lastv;
    if (t == 0) {
        double ts = 0.0;
        #pragma unroll
        for (int w = 0; w < MWRP; w++) ts += rs[w];
        atomicAdd(&g_loss, -ts);                    // NLL sign
        __threadfence();
        lastv = atomicAdd(&g_c2, 1u);
    }
    __syncthreads();
    if (lastv != NMB - 1) return;

    __threadfence();
    for (int i = t; i < out_size; i += MTHR) out[i] = 0.f;
    __syncthreads();
    if (t == 0) {
        out[0] = (float)g_loss;
        g_c2 = 0u;
    }
}

extern "C" void kernel_launch(void* const* d_in, const int* in_sizes, int n_in,
                              void* d_out, int out_size) {
    const float* segin    = (const float*)d_in[0];
    const float* edgein   = (const float*)d_in[1];
    const int*   segmask  = (const int*)d_in[2];
    const int*   edgemask = (const int*)d_in[3];
    float* out = (float*)d_out;

    dim3 hgrid(HB, NIMG);
    hist_kernel<<<hgrid, HTHR>>>(segmask, edgein, edgemask);
    main_kernel<<<NMB, MTHR>>>(segin, out, out_size);
}

// round 15
// speedup vs baseline: 1.5223x; 1.0573x over previous
#include <cuda_runtime.h>

#define CCLS 19
#define NIMG 4
#define HW   589824            /* 768*768 */
#define TOT  2359296           /* NIMG*HW */
#define GPI  147456            /* float4-groups per image (HW/4) */
#define TGP  589824            /* total float4-groups (NIMG*GPI) */

#define HTHR 256               /* hist threads/block */
#define HB   296               /* hist blocks per image: 4*296=1184 = 148 SMs * 8 */
#define NHB  (NIMG*HB)         /* 1184 = exactly one wave at 8 blocks/SM */
#define HWRP (HTHR/32)         /* 8 */

#define MTHR 256               /* main threads/block */
#define NMB  740               /* main blocks = 148 SMs * 5 resident, 1 wave */
#define MWRP (MTHR/32)         /* 8 */

#define PDL_TRIGGER()  asm volatile("griddepcontrol.launch_dependents;" ::: "memory")
#define PDL_WAIT()     asm volatile("griddepcontrol.wait;" ::: "memory")

// ---- static device scratch (no allocs) ----
__device__ unsigned char g_idx[TOT];          // per-pixel: tc + 19*(edge>0.8)
__device__ unsigned int  g_cnt38[NIMG][38];   // [n][idx] counts (int atomics, exact)
__device__ double g_bp, g_bn;
__device__ unsigned long long g_pc;
__device__ float  g_w[NIMG][38];              // [c]: wseg/den ; [19+c]: + 0.1*watt/denatt
__device__ double g_loss;
__device__ unsigned int g_c1 = 0, g_c2 = 0;   // self-resetting arrival counters

// ============================================================
// Kernel 1: histogram + BCE + idx pack; last block: weights + edge loss.
// Per-warp bins + shared atomics (1.2KB smem -> 8 blocks/SM, full wave).
// PDL: each block triggers launch_dependents once its results are fenced.
// ============================================================
__global__ __launch_bounds__(HTHR) void hist_kernel(
    const int* __restrict__ segmask, const float* __restrict__ edgein,
    const int* __restrict__ edgemask)
{
    __shared__ unsigned int cnt[HWRP][38];    // per-warp bins (spread-addr atomics)
    __shared__ float  sbp[HWRP], sbn[HWRP];
    __shared__ unsigned int spc[HWRP];

    const int n = blockIdx.y, b = blockIdx.x, t = threadIdx.x;
    const int wid = t >> 5, lid = t & 31;

    for (int i = t; i < HWRP * 38; i += HTHR) ((unsigned int*)cnt)[i] = 0u;
    __syncthreads();

    const int4*   sm4 = (const int4*)(segmask + (size_t)n * HW);
    const float4* e4p = (const float4*)(edgein  + (size_t)n * HW);
    const int4*   em4 = (const int4*)(edgemask + (size_t)n * HW);
    uchar4*       id4 = (uchar4*)g_idx + (size_t)n * GPI;

    float bp = 0.f, bn = 0.f; unsigned int pc = 0;

    for (int gi = b * HTHR + t; gi < GPI; gi += HB * HTHR) {
        const int4   tc = sm4[gi];
        const float4 e  = e4p[gi];
        const int4   em = em4[gi];

        const int i0 = tc.x + (e.x > 0.8f ? CCLS : 0);
        const int i1 = tc.y + (e.y > 0.8f ? CCLS : 0);
        const int i2 = tc.z + (e.z > 0.8f ? CCLS : 0);
        const int i3 = tc.w + (e.w > 0.8f ? CCLS : 0);
        atomicAdd(&cnt[wid][i0], 1u);
        atomicAdd(&cnt[wid][i1], 1u);
        atomicAdd(&cnt[wid][i2], 1u);
        atomicAdd(&cnt[wid][i3], 1u);
        id4[gi] = make_uchar4((unsigned char)i0, (unsigned char)i1,
                              (unsigned char)i2, (unsigned char)i3);

        #define BCE_PX(EJ, EMJ) do {                                          \
            const float bce = fmaxf((EJ), 0.f) - (EJ) * (float)(EMJ)          \
                            + __logf(1.f + __expf(-fabsf(EJ)));               \
            bp += (EMJ) ? bce : 0.f;                                          \
            bn += (EMJ) ? 0.f : bce;                                          \
            pc += (unsigned)(EMJ);                                            \
        } while (0)
        BCE_PX(e.x, em.x); BCE_PX(e.y, em.y); BCE_PX(e.z, em.z); BCE_PX(e.w, em.w);
        #undef BCE_PX
    }
    __syncthreads();

    // per-class reduce: 38 threads sum the 8 warp bins, one global atomic each
    if (t < 38) {
        unsigned int s = 0;
        #pragma unroll
        for (int w = 0; w < HWRP; w++) s += cnt[w][t];
        if (s) atomicAdd(&g_cnt38[n][t], s);
    }

    // BCE reduce: shuffle -> shared -> 3 global atomics per block
    #pragma unroll
    for (int o = 16; o; o >>= 1) {
        bp += __shfl_down_sync(0xffffffffu, bp, o);
        bn += __shfl_down_sync(0xffffffffu, bn, o);
        pc += __shfl_down_sync(0xffffffffu, pc, o);
    }
    if (lid == 0) { sbp[wid] = bp; sbn[wid] = bn; spc[wid] = pc; }
    __syncthreads();
    if (t == 0) {
        float tp = 0.f, tn = 0.f; unsigned int tpc = 0;
        #pragma unroll
        for (int w = 0; w < HWRP; w++) { tp += sbp[w]; tn += sbn[w]; tpc += spc[w]; }
        atomicAdd(&g_bp, (double)tp);
        atomicAdd(&g_bn, (double)tn);
        atomicAdd(&g_pc, (unsigned long long)tpc);
    }

    __threadfence();
    __shared__ unsigned int lastv;
    if (t == 0) lastv = atomicAdd(&g_c1, 1u);
    __syncthreads();
    if (lastv != NHB - 1) {
        PDL_TRIGGER();                       // this block's writes are fenced: allow dependents
        return;
    }

    // ---------- epilogue: one block, tiny data ----------
    __threadfence();
    __shared__ float sc[NIMG][38];
    __shared__ float dens[NIMG], dena[NIMG], tots[NIMG], tota[NIMG];

    if (t < NIMG * 38) {
        const int ni = t / 38, c = t - ni * 38;
        sc[ni][c] = (float)g_cnt38[ni][c];   // counts < 2^24: exact
        g_cnt38[ni][c] = 0u;                 // reset for next replay
    }
    __syncthreads();
    if (t < NIMG) {
        float tot = 0.f, ta = 0.f;
        #pragma unroll
        for (int c = 0; c < CCLS; c++) { tot += sc[t][c] + sc[t][CCLS + c]; ta += sc[t][CCLS + c]; }
        float ds = 0.f, da = 0.f;
        #pragma unroll
        for (int c = 0; c < CCLS; c++) {
            const float cs = sc[t][c] + sc[t][CCLS + c];
            const float ca = sc[t][CCLS + c];
            ds += (2.f - cs / tot) * cs;
            if (ta > 0.f) da += (2.f - ca / ta) * ca;
        }
        tots[t] = tot; tota[t] = ta; dens[t] = ds; dena[t] = da;
    }
    __syncthreads();
    if (t < NIMG * CCLS) {
        const int ni = t / CCLS, c = t - ni * CCLS;
        const float cs = sc[ni][c] + sc[ni][CCLS + c];
        const float ca = sc[ni][CCLS + c];
        const float ws = (2.f - cs / tots[ni]) / dens[ni];
        const float wa = (dena[ni] > 0.f) ? 0.1f * (2.f - ca / tota[ni]) / dena[ni] : 0.f;
        g_w[ni][c]        = ws;
        g_w[ni][CCLS + c] = ws + wa;
    }
    if (t == 0) {
        const double posn = (double)g_pc, negn = (double)TOT - posn;
        g_loss = 0.3 * (negn * g_bp + posn * g_bn) / ((double)TOT * (double)TOT);
        g_bp = 0.0; g_bn = 0.0; g_pc = 0ull;
        g_c1 = 0u;
    }
    __syncthreads();
    __threadfence();                         // g_w/g_loss visible before release
    PDL_TRIGGER();                           // final release: dependents may consume weights
}

// ============================================================
// Kernel 2: heavy pass over segin (+2.4MB idx). R14-proven hot loop.
// PDL: blocks launch during hist's drain; wait before consuming g_w/g_idx.
// ============================================================
__global__ __launch_bounds__(MTHR, 5) void main_kernel(
    const float* __restrict__ segin, float* __restrict__ out, int out_size)
{
    __shared__ float sw[NIMG][38];
    __shared__ double rs[MWRP];
    const int t = threadIdx.x;

    PDL_WAIT();                              // hist results (g_w, g_idx) now visible

    if (t < NIMG * 38) ((float*)sw)[t] = ((const float*)g_w)[t];
    __syncthreads();

    const float4* s4 = (const float4*)segin;
    const uchar4* i4 = (const uchar4*)g_idx;

    float acc = 0.f;

    #pragma unroll 1
    for (int g = blockIdx.x * MTHR + t; g < TGP; g += NMB * MTHR) {
        const int n = g / GPI;                       // 0..3, mul-shift
        const uchar4 id = i4[g];
        const float4* base = s4 + (size_t)n * (18 * GPI) + g;  // = n*19*GPI + gi

        const int t0 = id.x - (id.x >= CCLS ? CCLS : 0);
        const int t1 = id.y - (id.y >= CCLS ? CCLS : 0);
        const int t2 = id.z - (id.z >= CCLS ? CCLS : 0);
        const int t3 = id.w - (id.w >= CCLS ? CCLS : 0);

        float s0 = 0.f, s1 = 0.f, s2 = 0.f, s3 = 0.f;
        float x0 = 0.f, x1 = 0.f, x2 = 0.f, x3 = 0.f;
        #pragma unroll
        for (int c = 0; c < CCLS; c++) {
            const float4 v = __ldcs((const float4*)(base + (size_t)c * GPI));
            s0 += __expf(v.x); x0 = (c == t0) ? v.x : x0;
            s1 += __expf(v.y); x1 = (c == t1) ? v.y : x1;
            s2 += __expf(v.z); x2 = (c == t2) ? v.z : x2;
            s3 += __expf(v.w); x3 = (c == t3) ? v.w : x3;
        }
        const float* swn = &sw[n][0];
        acc += (x0 - __logf(s0)) * swn[id.x]
             + (x1 - __logf(s1)) * swn[id.y]
             + (x2 - __logf(s2)) * swn[id.z]
             + (x3 - __logf(s3)) * swn[id.w];
    }

    #pragma unroll
    for (int o = 16; o; o >>= 1) acc += __shfl_down_sync(0xffffffffu, acc, o);
    const int wid = t >> 5, lid = t & 31;
    if (lid == 0) rs[wid] = (double)acc;
    __syncthreads();

    __shared__ unsigned int lastv;
    if (t == 0) {
        double ts = 0.0;
        #pragma unroll
        for (int w = 0; w < MWRP; w++) ts += rs[w];
        atomicAdd(&g_loss, -ts);                    // NLL sign
        __threadfence();
        lastv = atomicAdd(&g_c2, 1u);
    }
    __syncthreads();
    if (lastv != NMB - 1) return;

    __threadfence();
    for (int i = t; i < out_size; i += MTHR) out[i] = 0.f;
    __syncthreads();
    if (t == 0) {
        out[0] = (float)g_loss;
        g_c2 = 0u;
    }
}

extern "C" void kernel_launch(void* const* d_in, const int* in_sizes, int n_in,
                              void* d_out, int out_size) {
    const float* segin    = (const float*)d_in[0];
    const float* edgein   = (const float*)d_in[1];
    const int*   segmask  = (const int*)d_in[2];
    const int*   edgemask = (const int*)d_in[3];
    float* out = (float*)d_out;

    dim3 hgrid(HB, NIMG);
    hist_kernel<<<hgrid, HTHR>>>(segmask, edgein, edgemask);

    // main: programmatic dependent launch — blocks spawn during hist's drain,
    // griddepcontrol.wait gates consumption of hist results.
    cudaLaunchConfig_t cfg = {};
    cfg.gridDim  = dim3(NMB);
    cfg.blockDim = dim3(MTHR);
    cfg.dynamicSmemBytes = 0;
    cfg.stream = 0;
    cudaLaunchAttribute attr[1];
    attr[0].id = cudaLaunchAttributeProgrammaticStreamSerialization;
    attr[0].val.programmaticStreamSerializationAllowed = 1;
    cfg.attrs = attr;
    cfg.numAttrs = 1;
    cudaLaunchKernelEx(&cfg, main_kernel, segin, out, out_size);
}